// round 12
// baseline (speedup 1.0000x reference)
#include <cuda_runtime.h>
#include <cuda_bf16.h>
#include <math.h>
#include <stdint.h>

#define FEAT 256
#define NQKV 768
#define NTOT 12288

// bf16 hi/lo splits (device globals: allocation-guard safe)
__device__ __nv_bfloat16 g_qh[NTOT * FEAT];
__device__ __nv_bfloat16 g_ql[NTOT * FEAT];
__device__ __nv_bfloat16 g_kh[NTOT * FEAT];
__device__ __nv_bfloat16 g_kl[NTOT * FEAT];
__device__ __nv_bfloat16 g_vth[FEAT * NTOT];   // V transposed: [d][key]
__device__ __nv_bfloat16 g_vtl[FEAT * NTOT];
// split inputs for the QKV HMMA GEMM
__device__ __nv_bfloat16 g_sh[NTOT * FEAT];
__device__ __nv_bfloat16 g_sl[NTOT * FEAT];
__device__ __nv_bfloat16 g_wth[NQKV * FEAT];   // W transposed: [n][k]
__device__ __nv_bfloat16 g_wtl[NQKV * FEAT];
// split-K attention scratch: 4 quarters
__device__ float g_acc[4 * NTOT * FEAT];
__device__ float g_ml[4 * NTOT * 2];

__constant__ int c_n_g[8]   = {2048, 1536, 1024, 2048, 512, 1792, 1280, 2048};
__constant__ int c_off_g[8] = {0, 2048, 3584, 4608, 6656, 7168, 8960, 10240};
// 768 quarter-CTAs, LPT order (8,8,8,7,6,5,4,2 iters per CTA)
__constant__ int c4_start[9] = {0, 128, 256, 384, 496, 592, 672, 736, 768};
__constant__ int c4_g[8]     = {0, 3, 7, 5, 1, 6, 2, 4};

// ---------------------------------------------------------------------------
// helpers
// ---------------------------------------------------------------------------
__device__ __forceinline__ uint32_t smem_u32(const void* p) {
    uint32_t a;
    asm("{ .reg .u64 t; cvta.to.shared.u64 t, %1; cvt.u32.u64 %0, t; }"
        : "=r"(a) : "l"(p));
    return a;
}
__device__ __forceinline__ void cp16(uint32_t dst, const void* src) {
    asm volatile(
        "{ .reg .u64 g; cvta.to.global.u64 g, %1;\n\t"
        "cp.async.cg.shared.global [%0], [g], 16; }"
        ::"r"(dst), "l"(src));
}
__device__ __forceinline__ void cp_commit() {
    asm volatile("cp.async.commit_group;" ::: "memory");
}
template <int N>
__device__ __forceinline__ void cp_wait() {
    asm volatile("cp.async.wait_group %0;" ::"n"(N) : "memory");
}
__device__ __forceinline__ void hmma(float* c, uint32_t a0, uint32_t a1,
                                     uint32_t a2, uint32_t a3,
                                     uint32_t b0, uint32_t b1) {
    asm volatile(
        "mma.sync.aligned.m16n8k16.row.col.f32.bf16.bf16.f32 "
        "{%0,%1,%2,%3}, {%4,%5,%6,%7}, {%8,%9}, {%0,%1,%2,%3};"
        : "+f"(c[0]), "+f"(c[1]), "+f"(c[2]), "+f"(c[3])
        : "r"(a0), "r"(a1), "r"(a2), "r"(a3), "r"(b0), "r"(b1));
}
__device__ __forceinline__ void ldm_x4(uint32_t& r0, uint32_t& r1, uint32_t& r2,
                                       uint32_t& r3, uint32_t addr) {
    asm volatile(
        "ldmatrix.sync.aligned.m8n8.x4.shared.b16 {%0,%1,%2,%3}, [%4];"
        : "=r"(r0), "=r"(r1), "=r"(r2), "=r"(r3) : "r"(addr));
}
__device__ __forceinline__ void split2(float x, __nv_bfloat16& h, __nv_bfloat16& l) {
    h = __float2bfloat16(x);
    l = __float2bfloat16(x - __bfloat162float(h));
}
__device__ __forceinline__ uint32_t packsplit_hi(float a, float b) {
    __nv_bfloat16 ha = __float2bfloat16(a), hb = __float2bfloat16(b);
    return (uint32_t)__bfloat16_as_ushort(ha) |
           ((uint32_t)__bfloat16_as_ushort(hb) << 16);
}
__device__ __forceinline__ uint32_t packsplit_lo(float a, float b) {
    __nv_bfloat16 ha = __float2bfloat16(a), hb = __float2bfloat16(b);
    __nv_bfloat16 la = __float2bfloat16(a - __bfloat162float(ha));
    __nv_bfloat16 lb = __float2bfloat16(b - __bfloat162float(hb));
    return (uint32_t)__bfloat16_as_ushort(la) |
           ((uint32_t)__bfloat16_as_ushort(lb) << 16);
}

// ---------------------------------------------------------------------------
// Kernel 0a/0b: input splits
// ---------------------------------------------------------------------------
__global__ __launch_bounds__(256) void split_s(const float* __restrict__ S) {
    int i4 = blockIdx.x * 256 + threadIdx.x;
    const float4 v = *(const float4*)&S[i4 * 4];
    __nv_bfloat16 h[4], l[4];
    split2(v.x, h[0], l[0]);
    split2(v.y, h[1], l[1]);
    split2(v.z, h[2], l[2]);
    split2(v.w, h[3], l[3]);
    uint2 ph, pl;
    ph.x = (uint32_t)__bfloat16_as_ushort(h[0]) |
           ((uint32_t)__bfloat16_as_ushort(h[1]) << 16);
    ph.y = (uint32_t)__bfloat16_as_ushort(h[2]) |
           ((uint32_t)__bfloat16_as_ushort(h[3]) << 16);
    pl.x = (uint32_t)__bfloat16_as_ushort(l[0]) |
           ((uint32_t)__bfloat16_as_ushort(l[1]) << 16);
    pl.y = (uint32_t)__bfloat16_as_ushort(l[2]) |
           ((uint32_t)__bfloat16_as_ushort(l[3]) << 16);
    *(uint2*)&g_sh[i4 * 4] = ph;
    *(uint2*)&g_sl[i4 * 4] = pl;
}

__global__ __launch_bounds__(256) void split_w(const float* __restrict__ W) {
    int t = blockIdx.x * 256 + threadIdx.x;
    int k = t / NQKV, n = t % NQKV;
    __nv_bfloat16 h, l;
    split2(W[t], h, l);
    g_wth[n * FEAT + k] = h;
    g_wtl[n * FEAT + k] = l;
}

// ---------------------------------------------------------------------------
// Kernel 1: QKV GEMM (R10 version — ldmatrix, single-sync pipeline)
// ---------------------------------------------------------------------------
#define GM_TOTAL 147456

__global__ __launch_bounds__(256, 1) void qkv_hmma(const float* __restrict__ bias) {
    extern __shared__ char smem[];
    const uint32_t sbase = smem_u32(smem);

    const int tid  = threadIdx.x;
    const int lane = tid & 31;
    const int warp = tid >> 5;
    const int mi   = warp >> 2;
    const int ni   = warp & 3;
    const int g    = lane >> 2;
    const int tg   = lane & 3;

    const int nblk = blockIdx.x;
    const int n0   = nblk * 128;
    const int m0   = blockIdx.y * 128;

    const uint32_t aOff = (uint32_t)(mi * 64 + (lane & 7) + (((lane >> 3) & 1) * 8)) * 144 +
                          (uint32_t)((lane >> 4) & 1) * 16;
    const uint32_t bOff = (uint32_t)(ni * 32 + (lane & 7) + ((lane >> 4) * 8)) * 144 +
                          (uint32_t)((lane >> 3) & 1) * 16;

    float cS[4][4][4];
#pragma unroll
    for (int a = 0; a < 4; a++)
#pragma unroll
        for (int b = 0; b < 4; b++)
#pragma unroll
            for (int c = 0; c < 4; c++) cS[a][b][c] = 0.f;

    auto load_stage = [&](int kc, uint32_t buf) {
#pragma unroll
        for (int p = 0; p < 8; p++) {
            int idx = p * 256 + tid;
            int comp = idx >> 10;
            int e = idx & 1023;
            int r = e >> 3, c16 = e & 7;
            cp16(sbase + buf + comp * 18432 + r * 144 + c16 * 16,
                 (comp ? g_sl : g_sh) + (m0 + r) * FEAT + kc * 64 + c16 * 8);
            cp16(sbase + 73728 + buf + comp * 18432 + r * 144 + c16 * 16,
                 (comp ? g_wtl : g_wth) + (n0 + r) * FEAT + kc * 64 + c16 * 8);
        }
    };

    load_stage(0, 0);
    cp_commit();

    for (int kc = 0; kc < 4; kc++) {
        cp_wait<0>();
        __syncthreads();
        if (kc < 3) {
            load_stage(kc + 1, ((kc + 1) & 1) ? 36864u : 0u);
            cp_commit();
        }
        const uint32_t abuf = sbase + ((kc & 1) ? 36864u : 0u);
        const uint32_t bbuf = abuf + 73728u;

#pragma unroll
        for (int st = 0; st < 4; st++) {
            const uint32_t so = (uint32_t)st * 32;
            uint32_t Ah[4][4], Al[4][4];
#pragma unroll
            for (int mt = 0; mt < 4; mt++) {
                ldm_x4(Ah[mt][0], Ah[mt][1], Ah[mt][2], Ah[mt][3],
                       abuf + (uint32_t)mt * 2304 + aOff + so);
                ldm_x4(Al[mt][0], Al[mt][1], Al[mt][2], Al[mt][3],
                       abuf + 18432u + (uint32_t)mt * 2304 + aOff + so);
            }
#pragma unroll
            for (int jp = 0; jp < 2; jp++) {
                uint32_t h0, h1, h2, h3, l0, l1, l2, l3;
                ldm_x4(h0, h1, h2, h3, bbuf + (uint32_t)jp * 2304 + bOff + so);
                ldm_x4(l0, l1, l2, l3, bbuf + 18432u + (uint32_t)jp * 2304 + bOff + so);
#pragma unroll
                for (int mt = 0; mt < 4; mt++) {
                    hmma(cS[mt][jp * 2], Ah[mt][0], Ah[mt][1], Ah[mt][2],
                         Ah[mt][3], h0, h1);
                    hmma(cS[mt][jp * 2], Ah[mt][0], Ah[mt][1], Ah[mt][2],
                         Ah[mt][3], l0, l1);
                    hmma(cS[mt][jp * 2], Al[mt][0], Al[mt][1], Al[mt][2],
                         Al[mt][3], h0, h1);
                    hmma(cS[mt][jp * 2 + 1], Ah[mt][0], Ah[mt][1], Ah[mt][2],
                         Ah[mt][3], h2, h3);
                    hmma(cS[mt][jp * 2 + 1], Ah[mt][0], Ah[mt][1], Ah[mt][2],
                         Ah[mt][3], l2, l3);
                    hmma(cS[mt][jp * 2 + 1], Al[mt][0], Al[mt][1], Al[mt][2],
                         Al[mt][3], h2, h3);
                }
            }
        }
    }

    __syncthreads();

    if (nblk < 4) {
        __nv_bfloat16* Bh = (nblk < 2) ? g_qh : g_kh;
        __nv_bfloat16* Bl = (nblk < 2) ? g_ql : g_kl;
        const int cbase0 = (nblk & 1) * 128 + ni * 32;
#pragma unroll
        for (int mt = 0; mt < 4; mt++) {
#pragma unroll
            for (int j = 0; j < 4; j++) {
                const int cc = cbase0 + j * 8 + tg * 2;
                const float b0 = bias[(nblk < 2 ? 0 : 256) + cc];
                const float b1 = bias[(nblk < 2 ? 0 : 256) + cc + 1];
#pragma unroll
                for (int p = 0; p < 2; p++) {
                    const int row = m0 + mi * 64 + mt * 16 + g + p * 8;
                    const float v0 = cS[mt][j][p * 2] + b0;
                    const float v1 = cS[mt][j][p * 2 + 1] + b1;
                    *(uint32_t*)&Bh[row * FEAT + cc] = packsplit_hi(v0, v1);
                    *(uint32_t*)&Bl[row * FEAT + cc] = packsplit_lo(v0, v1);
                }
            }
        }
    } else {
        const int d0 = n0 - 512;
#pragma unroll
        for (int mt = 0; mt < 4; mt++) {
#pragma unroll
            for (int j = 0; j < 4; j++) {
                const int nn = ni * 32 + j * 8 + tg * 2;
                const float b0 = bias[512 + d0 + nn];
                const float b1 = bias[512 + d0 + nn + 1];
#pragma unroll
                for (int p = 0; p < 2; p++) {
                    const int mm = mi * 64 + mt * 16 + g + p * 8;
                    const float v0 = cS[mt][j][p * 2] + b0;
                    const float v1 = cS[mt][j][p * 2 + 1] + b1;
                    __nv_bfloat16 h0, l0, h1, l1;
                    split2(v0, h0, l0);
                    split2(v1, h1, l1);
                    *(__nv_bfloat16*)(smem + nn * 256 + mm * 2) = h0;
                    *(__nv_bfloat16*)(smem + (nn + 1) * 256 + mm * 2) = h1;
                    *(__nv_bfloat16*)(smem + 32768 + nn * 256 + mm * 2) = l0;
                    *(__nv_bfloat16*)(smem + 32768 + (nn + 1) * 256 + mm * 2) = l1;
                }
            }
        }
        __syncthreads();
#pragma unroll
        for (int rr = 0; rr < 16; rr++) {
            const int r = warp + rr * 8;
            uint2 vh = *(uint2*)(smem + r * 256 + lane * 8);
            uint2 vl = *(uint2*)(smem + 32768 + r * 256 + lane * 8);
            *(uint2*)&g_vth[(size_t)(d0 + r) * NTOT + m0 + lane * 4] = vh;
            *(uint2*)&g_vtl[(size_t)(d0 + r) * NTOT + m0 + lane * 4] = vl;
        }
    }
}

// ---------------------------------------------------------------------------
// Kernel 2: 16-warp work-split FA2 attention, split-K 4.
// CTA = 512 thr. Warp (mi,nj): S[16 rows, 16 cols], O[16 rows, douts nj*16/64-chunk].
// P round-trips through SMEM once per iter. 1 CTA/SM, 4 warps/SMSP.
// ---------------------------------------------------------------------------
#define QH_OFF 0
#define QL_OFF 33792
#define B0_OFF 67584
#define B1_OFF 86016
#define PH_OFF 104448
#define PL_OFF 113664
#define R1_OFF 122880
#define R2_OFF 123904
#define SM_ATT 124928

__global__ __launch_bounds__(512, 1) void attn_q() {
    extern __shared__ char smem[];
    const uint32_t sbase = smem_u32(smem);

    const int tid  = threadIdx.x;
    const int lane = tid & 31;
    const int warp = tid >> 5;
    const int mi   = warp & 3;          // row block (16 rows)
    const int nj   = warp >> 2;         // col/dout sub-block (16)
    const int g    = lane >> 2;
    const int tg   = lane & 3;

    // ldmatrix lane offsets
    const uint32_t bOffK = (uint32_t)(nj * 16 + ((lane >> 4) * 8) + (lane & 7)) * 144 +
                           (uint32_t)((lane >> 3) & 1) * 16;
    const uint32_t aOffQ = (uint32_t)(mi * 16 + (lane & 7) + (((lane >> 3) & 1) * 8)) * 528 +
                           (uint32_t)((lane >> 4) & 1) * 16;
    const uint32_t aOffP = (uint32_t)(mi * 16 + (lane & 7) + (((lane >> 3) & 1) * 8)) * 144 +
                           (uint32_t)((lane >> 4) & 1) * 16;

    // bid -> (graph, tile, quarter) via LPT schedule
    int s = 0;
    while (s < 7 && (int)blockIdx.x >= c4_start[s + 1]) s++;
    const int li   = blockIdx.x - c4_start[s];
    const int gr   = c4_g[s];
    const int tile = li >> 2;
    const int quarter = li & 3;
    const int nk   = c_n_g[gr];
    const int koff = c_off_g[gr];
    const int q0   = koff + tile * 64;
    const int kv0  = koff + quarter * (nk >> 2);
    const int n_kt = nk >> 8;

    auto load_k = [&](uint32_t dst, int kb, int dc) {
#pragma unroll
        for (int p = 0; p < 2; p++) {
            int idx = p * 512 + tid;
            int comp = idx >> 9;
            int e = idx & 511;
            int r = e >> 3, c16 = e & 7;
            cp16(dst + comp * 9216 + r * 144 + c16 * 16,
                 (comp ? g_kl : g_kh) + (kb + r) * FEAT + dc * 64 + c16 * 8);
        }
    };
    auto load_v = [&](uint32_t dst, int kb, int vc) {
#pragma unroll
        for (int p = 0; p < 2; p++) {
            int idx = p * 512 + tid;
            int comp = idx >> 9;
            int e = idx & 511;
            int r = e >> 3, c16 = e & 7;
            cp16(dst + comp * 9216 + r * 144 + c16 * 16,
                 (comp ? g_vtl : g_vth) + (size_t)(vc * 64 + r) * NTOT + kb + c16 * 8);
        }
    };

    // resident Q hi/lo [64][256], row stride 528B
#pragma unroll
    for (int p = 0; p < 8; p++) {
        int idx = p * 512 + tid;
        int comp = idx >> 11;
        int e = idx & 2047;
        int r = e >> 5, c16 = e & 31;
        cp16(sbase + (comp ? QL_OFF : QH_OFF) + r * 528 + c16 * 16,
             (comp ? g_ql : g_qh) + (q0 + r) * FEAT + c16 * 8);
    }
    cp_commit();
    cp_wait<0>();
    __syncthreads();

    float* red1 = (float*)(smem + R1_OFF);
    float* red2 = (float*)(smem + R2_OFF);
    uint32_t* ph32 = (uint32_t*)(smem + PH_OFF);
    uint32_t* pl32 = (uint32_t*)(smem + PL_OFF);

    float O[4][2][4];
#pragma unroll
    for (int a = 0; a < 4; a++)
#pragma unroll
        for (int b = 0; b < 2; b++)
#pragma unroll
            for (int c = 0; c < 4; c++) O[a][b][c] = 0.f;
    float M0 = -INFINITY, M1 = -INFINITY, L0 = 0.f, L1 = 0.f;
    const float scale = 0.0625f;

    const int row0 = mi * 16 + g;       // tile-local rows this thread owns
    const int row1 = row0 + 8;

    load_k(sbase + B0_OFF, kv0, 0);
    cp_commit();

    for (int kt = 0; kt < n_kt; kt++) {
        const int kb = kv0 + kt * 64;

        float cS[2][4];
#pragma unroll
        for (int j = 0; j < 2; j++)
#pragma unroll
            for (int c = 0; c < 4; c++) cS[j][c] = 0.f;

        // ---------- S phase: K chunks 0..3 ----------
        for (int dc = 0; dc < 4; dc++) {
            cp_wait<0>();
            __syncthreads();
            if (dc < 3)
                load_k(sbase + (((dc + 1) & 1) ? B1_OFF : B0_OFF), kb, dc + 1);
            else
                load_v(sbase + B0_OFF, kb, 0);
            cp_commit();

            const uint32_t khbuf = sbase + ((dc & 1) ? B1_OFF : B0_OFF);
            const uint32_t klbuf = khbuf + 9216;

#pragma unroll
            for (int st = 0; st < 4; st++) {
                const uint32_t stoff = (uint32_t)st * 32;
                uint32_t ah0, ah1, ah2, ah3, al0, al1, al2, al3;
                ldm_x4(ah0, ah1, ah2, ah3,
                       sbase + QH_OFF + aOffQ + (uint32_t)(dc * 4 + st) * 32);
                ldm_x4(al0, al1, al2, al3,
                       sbase + QL_OFF + aOffQ + (uint32_t)(dc * 4 + st) * 32);
                uint32_t h0, h1, h2, h3, l0, l1, l2, l3;
                ldm_x4(h0, h1, h2, h3, khbuf + bOffK + stoff);
                ldm_x4(l0, l1, l2, l3, klbuf + bOffK + stoff);
                hmma(cS[0], ah0, ah1, ah2, ah3, h0, h1);
                hmma(cS[1], ah0, ah1, ah2, ah3, h2, h3);
                hmma(cS[0], ah0, ah1, ah2, ah3, l0, l1);
                hmma(cS[1], ah0, ah1, ah2, ah3, l2, l3);
                hmma(cS[0], al0, al1, al2, al3, h0, h1);
                hmma(cS[1], al0, al1, al2, al3, h2, h3);
            }
        }

        // ---------- softmax: cross-warp (4 nj groups) ----------
        float mx0 = fmaxf(fmaxf(cS[0][0], cS[0][1]), fmaxf(cS[1][0], cS[1][1]));
        float mx1 = fmaxf(fmaxf(cS[0][2], cS[0][3]), fmaxf(cS[1][2], cS[1][3]));
        mx0 *= scale;
        mx1 *= scale;
        mx0 = fmaxf(mx0, __shfl_xor_sync(0xffffffffu, mx0, 1));
        mx0 = fmaxf(mx0, __shfl_xor_sync(0xffffffffu, mx0, 2));
        mx1 = fmaxf(mx1, __shfl_xor_sync(0xffffffffu, mx1, 1));
        mx1 = fmaxf(mx1, __shfl_xor_sync(0xffffffffu, mx1, 2));
        if (tg == 0) {
            red1[nj * 64 + row0] = mx0;
            red1[nj * 64 + row1] = mx1;
        }
        __syncthreads();
        float mall0 = fmaxf(fmaxf(red1[row0], red1[64 + row0]),
                            fmaxf(red1[128 + row0], red1[192 + row0]));
        float mall1 = fmaxf(fmaxf(red1[row1], red1[64 + row1]),
                            fmaxf(red1[128 + row1], red1[192 + row1]));
        const float mn0 = fmaxf(M0, mall0);
        const float mn1 = fmaxf(M1, mall1);
        const float alpha0 = __expf(M0 - mn0);
        const float alpha1 = __expf(M1 - mn1);
        M0 = mn0;
        M1 = mn1;
        float ps0 = 0.f, ps1 = 0.f;
#pragma unroll
        for (int j = 0; j < 2; j++) {
            cS[j][0] = __expf(cS[j][0] * scale - mn0);
            cS[j][1] = __expf(cS[j][1] * scale - mn0);
            cS[j][2] = __expf(cS[j][2] * scale - mn1);
            cS[j][3] = __expf(cS[j][3] * scale - mn1);
            ps0 += cS[j][0] + cS[j][1];
            ps1 += cS[j][2] + cS[j][3];
        }
        ps0 += __shfl_xor_sync(0xffffffffu, ps0, 1);
        ps0 += __shfl_xor_sync(0xffffffffu, ps0, 2);
        ps1 += __shfl_xor_sync(0xffffffffu, ps1, 1);
        ps1 += __shfl_xor_sync(0xffffffffu, ps1, 2);

        // write P hi/lo to smem (row stride 144B), then sum-exchange
#pragma unroll
        for (int j = 0; j < 2; j++) {
            const int colw = (nj * 16 + j * 8 + tg * 2) >> 1;   // u32 index in row
            ph32[row0 * 36 + colw] = packsplit_hi(cS[j][0], cS[j][1]);
            ph32[row1 * 36 + colw] = packsplit_hi(cS[j][2], cS[j][3]);
            pl32[row0 * 36 + colw] = packsplit_lo(cS[j][0], cS[j][1]);
            pl32[row1 * 36 + colw] = packsplit_lo(cS[j][2], cS[j][3]);
        }
        if (tg == 0) {
            red2[nj * 64 + row0] = ps0;
            red2[nj * 64 + row1] = ps1;
        }
        __syncthreads();
        const float ls0 = red2[row0] + red2[64 + row0] + red2[128 + row0] +
                          red2[192 + row0];
        const float ls1 = red2[row1] + red2[64 + row1] + red2[128 + row1] +
                          red2[192 + row1];
        L0 = L0 * alpha0 + ls0;
        L1 = L1 * alpha1 + ls1;

        const bool need_rescale =
            !__all_sync(0xffffffffu, (alpha0 == 1.0f) & (alpha1 == 1.0f));
        if (need_rescale) {
#pragma unroll
            for (int a = 0; a < 4; a++)
#pragma unroll
                for (int b = 0; b < 2; b++) {
                    O[a][b][0] *= alpha0;
                    O[a][b][1] *= alpha0;
                    O[a][b][2] *= alpha1;
                    O[a][b][3] *= alpha1;
                }
        }

        // load P A-frags (full 64 keys, reused across all V chunks)
        uint32_t PAh[4][4], PAl[4][4];
#pragma unroll
        for (int ks = 0; ks < 4; ks++) {
            ldm_x4(PAh[ks][0], PAh[ks][1], PAh[ks][2], PAh[ks][3],
                   sbase + PH_OFF + aOffP + (uint32_t)ks * 32);
            ldm_x4(PAl[ks][0], PAl[ks][1], PAl[ks][2], PAl[ks][3],
                   sbase + PL_OFF + aOffP + (uint32_t)ks * 32);
        }

        // ---------- PV phase: V chunks 0..3 (douts vc*64..+64) ----------
        for (int vc = 0; vc < 4; vc++) {
            cp_wait<0>();
            __syncthreads();
            if (vc < 3) {
                load_v(sbase + (((vc + 1) & 1) ? B1_OFF : B0_OFF), kb, vc + 1);
                cp_commit();
            } else if (kt + 1 < n_kt) {
                load_k(sbase + B0_OFF, kb + 64, 0);
                cp_commit();
            }

            const uint32_t vhbuf = sbase + ((vc & 1) ? B1_OFF : B0_OFF);
            const uint32_t vlbuf = vhbuf + 9216;

#pragma unroll
            for (int st = 0; st < 4; st++) {
                const uint32_t stoff = (uint32_t)st * 32;
                uint32_t h0, h1, h2, h3, l0, l1, l2, l3;
                ldm_x4(h0, h1, h2, h3, vhbuf + bOffK + stoff);
                ldm_x4(l0, l1, l2, l3, vlbuf + bOffK + stoff);
                hmma(O[vc][0], PAh[st][0], PAh[st][1], PAh[st][2], PAh[st][3],
                     h0, h1);
                hmma(O[vc][1], PAh[st][0], PAh[st][1], PAh[st][2], PAh[st][3],
                     h2, h3);
                hmma(O[vc][0], PAh[st][0], PAh[st][1], PAh[st][2], PAh[st][3],
                     l0, l1);
                hmma(O[vc][1], PAh[st][0], PAh[st][1], PAh[st][2], PAh[st][3],
                     l2, l3);
                hmma(O[vc][0], PAl[st][0], PAl[st][1], PAl[st][2], PAl[st][3],
                     h0, h1);
                hmma(O[vc][1], PAl[st][0], PAl[st][1], PAl[st][2], PAl[st][3],
                     h2, h3);
            }
        }
    }

    // ---------- epilogue: unnormalized partials + (M, L) ----------
    const int gr0 = q0 + row0;
    const int gr1 = q0 + row1;
    float* acc = g_acc + (size_t)quarter * NTOT * FEAT;
#pragma unroll
    for (int vc = 0; vc < 4; vc++)
#pragma unroll
        for (int j = 0; j < 2; j++) {
            const int col = vc * 64 + nj * 16 + j * 8 + tg * 2;
            float2 o0, o1;
            o0.x = O[vc][j][0];
            o0.y = O[vc][j][1];
            o1.x = O[vc][j][2];
            o1.y = O[vc][j][3];
            *(float2*)&acc[(size_t)gr0 * FEAT + col] = o0;
            *(float2*)&acc[(size_t)gr1 * FEAT + col] = o1;
        }
    if (nj == 0 && tg == 0) {
        float* ml = g_ml + (size_t)quarter * NTOT * 2;
        ml[gr0 * 2 + 0] = M0;
        ml[gr0 * 2 + 1] = L0;
        ml[gr1 * 2 + 0] = M1;
        ml[gr1 * 2 + 1] = L1;
    }
}

// ---------------------------------------------------------------------------
// Kernel 3: combine the four key-quarter partials
// ---------------------------------------------------------------------------
__global__ __launch_bounds__(256) void combine(float* __restrict__ out) {
    const int idx = blockIdx.x * 256 + threadIdx.x;
    const int row = idx >> 6;
    const int col = (idx & 63) * 4;

    float m[4], l[4];
#pragma unroll
    for (int q = 0; q < 4; q++) {
        m[q] = g_ml[(size_t)q * NTOT * 2 + row * 2 + 0];
        l[q] = g_ml[(size_t)q * NTOT * 2 + row * 2 + 1];
    }
    float M = fmaxf(fmaxf(m[0], m[1]), fmaxf(m[2], m[3]));
    float a[4], denom = 0.f;
#pragma unroll
    for (int q = 0; q < 4; q++) {
        a[q] = __expf(m[q] - M);
        denom += a[q] * l[q];
    }
    const float inv = 1.0f / denom;

    float4 o = make_float4(0.f, 0.f, 0.f, 0.f);
#pragma unroll
    for (int q = 0; q < 4; q++) {
        const float4 p =
            *(const float4*)&g_acc[(size_t)q * NTOT * FEAT + (size_t)row * FEAT + col];
        o.x += a[q] * p.x;
        o.y += a[q] * p.y;
        o.z += a[q] * p.z;
        o.w += a[q] * p.w;
    }
    o.x *= inv;
    o.y *= inv;
    o.z *= inv;
    o.w *= inv;
    *(float4*)&out[(size_t)row * FEAT + col] = o;
}

// ---------------------------------------------------------------------------
extern "C" void kernel_launch(void* const* d_in, const int* in_sizes, int n_in,
                              void* d_out, int out_size) {
    const float* s    = (const float*)d_in[0];   // [12288, 256]
    const float* W    = (const float*)d_in[1];   // [256, 768]
    const float* bias = (const float*)d_in[2];   // [768]
    float* out = (float*)d_out;                  // [12288, 256]

    cudaFuncSetAttribute(qkv_hmma, cudaFuncAttributeMaxDynamicSharedMemorySize,
                         GM_TOTAL);
    cudaFuncSetAttribute(attn_q, cudaFuncAttributeMaxDynamicSharedMemorySize,
                         SM_ATT);

    split_s<<<3072, 256>>>(s);
    split_w<<<768, 256>>>(W);
    qkv_hmma<<<dim3(6, 96), 256, GM_TOTAL>>>(bias);
    attn_q<<<768, 512, SM_ATT>>>();
    combine<<<3072, 256>>>(out);
}

// round 13
// speedup vs baseline: 1.0752x; 1.0752x over previous
#include <cuda_runtime.h>
#include <cuda_bf16.h>
#include <math.h>
#include <stdint.h>

#define FEAT 256
#define NQKV 768
#define NTOT 12288

// bf16 hi/lo splits (device globals: allocation-guard safe)
__device__ __nv_bfloat16 g_qh[NTOT * FEAT];
__device__ __nv_bfloat16 g_ql[NTOT * FEAT];
__device__ __nv_bfloat16 g_kh[NTOT * FEAT];
__device__ __nv_bfloat16 g_kl[NTOT * FEAT];
__device__ __nv_bfloat16 g_vth[FEAT * NTOT];   // V transposed: [d][key]
__device__ __nv_bfloat16 g_vtl[FEAT * NTOT];
// split inputs for the QKV HMMA GEMM
__device__ __nv_bfloat16 g_sh[NTOT * FEAT];
__device__ __nv_bfloat16 g_sl[NTOT * FEAT];
__device__ __nv_bfloat16 g_wth[NQKV * FEAT];   // W transposed: [n][k]
__device__ __nv_bfloat16 g_wtl[NQKV * FEAT];
// split-K attention scratch (2 halves)
__device__ float g_acc[2 * NTOT * FEAT];
__device__ float g_ml[2 * NTOT * 2];

__constant__ int c_n_g[8]   = {2048, 1536, 1024, 2048, 512, 1792, 1280, 2048};
__constant__ int c_off_g[8] = {0, 2048, 3584, 4608, 6656, 7168, 8960, 10240};
// 384 half-CTAs, LPT order
__constant__ int c2_start[9] = {0, 64, 128, 192, 248, 296, 336, 368, 384};
__constant__ int c2_g[8]     = {0, 3, 7, 5, 1, 6, 2, 4};

// ---------------------------------------------------------------------------
// helpers
// ---------------------------------------------------------------------------
__device__ __forceinline__ uint32_t smem_u32(const void* p) {
    uint32_t a;
    asm("{ .reg .u64 t; cvta.to.shared.u64 t, %1; cvt.u32.u64 %0, t; }"
        : "=r"(a) : "l"(p));
    return a;
}
__device__ __forceinline__ void cp16(uint32_t dst, const void* src) {
    asm volatile(
        "{ .reg .u64 g; cvta.to.global.u64 g, %1;\n\t"
        "cp.async.cg.shared.global [%0], [g], 16; }"
        ::"r"(dst), "l"(src));
}
__device__ __forceinline__ void cp_commit() {
    asm volatile("cp.async.commit_group;" ::: "memory");
}
template <int N>
__device__ __forceinline__ void cp_wait() {
    asm volatile("cp.async.wait_group %0;" ::"n"(N) : "memory");
}
__device__ __forceinline__ void hmma(float* c, uint32_t a0, uint32_t a1,
                                     uint32_t a2, uint32_t a3,
                                     uint32_t b0, uint32_t b1) {
    asm volatile(
        "mma.sync.aligned.m16n8k16.row.col.f32.bf16.bf16.f32 "
        "{%0,%1,%2,%3}, {%4,%5,%6,%7}, {%8,%9}, {%0,%1,%2,%3};"
        : "+f"(c[0]), "+f"(c[1]), "+f"(c[2]), "+f"(c[3])
        : "r"(a0), "r"(a1), "r"(a2), "r"(a3), "r"(b0), "r"(b1));
}
__device__ __forceinline__ void ldm_x4(uint32_t& r0, uint32_t& r1, uint32_t& r2,
                                       uint32_t& r3, uint32_t addr) {
    asm volatile(
        "ldmatrix.sync.aligned.m8n8.x4.shared.b16 {%0,%1,%2,%3}, [%4];"
        : "=r"(r0), "=r"(r1), "=r"(r2), "=r"(r3) : "r"(addr));
}
__device__ __forceinline__ void split2(float x, __nv_bfloat16& h, __nv_bfloat16& l) {
    h = __float2bfloat16(x);
    l = __float2bfloat16(x - __bfloat162float(h));
}
__device__ __forceinline__ uint32_t packsplit_hi(float a, float b) {
    __nv_bfloat16 ha = __float2bfloat16(a), hb = __float2bfloat16(b);
    return (uint32_t)__bfloat16_as_ushort(ha) |
           ((uint32_t)__bfloat16_as_ushort(hb) << 16);
}
__device__ __forceinline__ uint32_t packsplit_lo(float a, float b) {
    __nv_bfloat16 ha = __float2bfloat16(a), hb = __float2bfloat16(b);
    __nv_bfloat16 la = __float2bfloat16(a - __bfloat162float(ha));
    __nv_bfloat16 lb = __float2bfloat16(b - __bfloat162float(hb));
    return (uint32_t)__bfloat16_as_ushort(la) |
           ((uint32_t)__bfloat16_as_ushort(lb) << 16);
}

// ---------------------------------------------------------------------------
// Kernel 0a/0b: input splits
// ---------------------------------------------------------------------------
__global__ __launch_bounds__(256) void split_s(const float* __restrict__ S) {
    int i4 = blockIdx.x * 256 + threadIdx.x;
    const float4 v = *(const float4*)&S[i4 * 4];
    __nv_bfloat16 h[4], l[4];
    split2(v.x, h[0], l[0]);
    split2(v.y, h[1], l[1]);
    split2(v.z, h[2], l[2]);
    split2(v.w, h[3], l[3]);
    uint2 ph, pl;
    ph.x = (uint32_t)__bfloat16_as_ushort(h[0]) |
           ((uint32_t)__bfloat16_as_ushort(h[1]) << 16);
    ph.y = (uint32_t)__bfloat16_as_ushort(h[2]) |
           ((uint32_t)__bfloat16_as_ushort(h[3]) << 16);
    pl.x = (uint32_t)__bfloat16_as_ushort(l[0]) |
           ((uint32_t)__bfloat16_as_ushort(l[1]) << 16);
    pl.y = (uint32_t)__bfloat16_as_ushort(l[2]) |
           ((uint32_t)__bfloat16_as_ushort(l[3]) << 16);
    *(uint2*)&g_sh[i4 * 4] = ph;
    *(uint2*)&g_sl[i4 * 4] = pl;
}

__global__ __launch_bounds__(256) void split_w(const float* __restrict__ W) {
    int t = blockIdx.x * 256 + threadIdx.x;
    int k = t / NQKV, n = t % NQKV;
    __nv_bfloat16 h, l;
    split2(W[t], h, l);
    g_wth[n * FEAT + k] = h;
    g_wtl[n * FEAT + k] = l;
}

// ---------------------------------------------------------------------------
// Kernel 1: QKV GEMM (R10 version — ldmatrix, single-sync pipeline)
// ---------------------------------------------------------------------------
#define GM_TOTAL 147456

__global__ __launch_bounds__(256, 1) void qkv_hmma(const float* __restrict__ bias) {
    extern __shared__ char smem[];
    const uint32_t sbase = smem_u32(smem);

    const int tid  = threadIdx.x;
    const int lane = tid & 31;
    const int warp = tid >> 5;
    const int mi   = warp >> 2;
    const int ni   = warp & 3;
    const int g    = lane >> 2;
    const int tg   = lane & 3;

    const int nblk = blockIdx.x;
    const int n0   = nblk * 128;
    const int m0   = blockIdx.y * 128;

    const uint32_t aOff = (uint32_t)(mi * 64 + (lane & 7) + (((lane >> 3) & 1) * 8)) * 144 +
                          (uint32_t)((lane >> 4) & 1) * 16;
    const uint32_t bOff = (uint32_t)(ni * 32 + (lane & 7) + ((lane >> 4) * 8)) * 144 +
                          (uint32_t)((lane >> 3) & 1) * 16;

    float cS[4][4][4];
#pragma unroll
    for (int a = 0; a < 4; a++)
#pragma unroll
        for (int b = 0; b < 4; b++)
#pragma unroll
            for (int c = 0; c < 4; c++) cS[a][b][c] = 0.f;

    auto load_stage = [&](int kc, uint32_t buf) {
#pragma unroll
        for (int p = 0; p < 8; p++) {
            int idx = p * 256 + tid;
            int comp = idx >> 10;
            int e = idx & 1023;
            int r = e >> 3, c16 = e & 7;
            cp16(sbase + buf + comp * 18432 + r * 144 + c16 * 16,
                 (comp ? g_sl : g_sh) + (m0 + r) * FEAT + kc * 64 + c16 * 8);
            cp16(sbase + 73728 + buf + comp * 18432 + r * 144 + c16 * 16,
                 (comp ? g_wtl : g_wth) + (n0 + r) * FEAT + kc * 64 + c16 * 8);
        }
    };

    load_stage(0, 0);
    cp_commit();

    for (int kc = 0; kc < 4; kc++) {
        cp_wait<0>();
        __syncthreads();
        if (kc < 3) {
            load_stage(kc + 1, ((kc + 1) & 1) ? 36864u : 0u);
            cp_commit();
        }
        const uint32_t abuf = sbase + ((kc & 1) ? 36864u : 0u);
        const uint32_t bbuf = abuf + 73728u;

#pragma unroll
        for (int st = 0; st < 4; st++) {
            const uint32_t so = (uint32_t)st * 32;
            uint32_t Ah[4][4], Al[4][4];
#pragma unroll
            for (int mt = 0; mt < 4; mt++) {
                ldm_x4(Ah[mt][0], Ah[mt][1], Ah[mt][2], Ah[mt][3],
                       abuf + (uint32_t)mt * 2304 + aOff + so);
                ldm_x4(Al[mt][0], Al[mt][1], Al[mt][2], Al[mt][3],
                       abuf + 18432u + (uint32_t)mt * 2304 + aOff + so);
            }
#pragma unroll
            for (int jp = 0; jp < 2; jp++) {
                uint32_t h0, h1, h2, h3, l0, l1, l2, l3;
                ldm_x4(h0, h1, h2, h3, bbuf + (uint32_t)jp * 2304 + bOff + so);
                ldm_x4(l0, l1, l2, l3, bbuf + 18432u + (uint32_t)jp * 2304 + bOff + so);
#pragma unroll
                for (int mt = 0; mt < 4; mt++) {
                    hmma(cS[mt][jp * 2], Ah[mt][0], Ah[mt][1], Ah[mt][2],
                         Ah[mt][3], h0, h1);
                    hmma(cS[mt][jp * 2], Ah[mt][0], Ah[mt][1], Ah[mt][2],
                         Ah[mt][3], l0, l1);
                    hmma(cS[mt][jp * 2], Al[mt][0], Al[mt][1], Al[mt][2],
                         Al[mt][3], h0, h1);
                    hmma(cS[mt][jp * 2 + 1], Ah[mt][0], Ah[mt][1], Ah[mt][2],
                         Ah[mt][3], h2, h3);
                    hmma(cS[mt][jp * 2 + 1], Ah[mt][0], Ah[mt][1], Ah[mt][2],
                         Ah[mt][3], l2, l3);
                    hmma(cS[mt][jp * 2 + 1], Al[mt][0], Al[mt][1], Al[mt][2],
                         Al[mt][3], h2, h3);
                }
            }
        }
    }

    __syncthreads();

    if (nblk < 4) {
        __nv_bfloat16* Bh = (nblk < 2) ? g_qh : g_kh;
        __nv_bfloat16* Bl = (nblk < 2) ? g_ql : g_kl;
        const int cbase0 = (nblk & 1) * 128 + ni * 32;
#pragma unroll
        for (int mt = 0; mt < 4; mt++) {
#pragma unroll
            for (int j = 0; j < 4; j++) {
                const int cc = cbase0 + j * 8 + tg * 2;
                const float b0 = bias[(nblk < 2 ? 0 : 256) + cc];
                const float b1 = bias[(nblk < 2 ? 0 : 256) + cc + 1];
#pragma unroll
                for (int p = 0; p < 2; p++) {
                    const int row = m0 + mi * 64 + mt * 16 + g + p * 8;
                    const float v0 = cS[mt][j][p * 2] + b0;
                    const float v1 = cS[mt][j][p * 2 + 1] + b1;
                    *(uint32_t*)&Bh[row * FEAT + cc] = packsplit_hi(v0, v1);
                    *(uint32_t*)&Bl[row * FEAT + cc] = packsplit_lo(v0, v1);
                }
            }
        }
    } else {
        const int d0 = n0 - 512;
#pragma unroll
        for (int mt = 0; mt < 4; mt++) {
#pragma unroll
            for (int j = 0; j < 4; j++) {
                const int nn = ni * 32 + j * 8 + tg * 2;
                const float b0 = bias[512 + d0 + nn];
                const float b1 = bias[512 + d0 + nn + 1];
#pragma unroll
                for (int p = 0; p < 2; p++) {
                    const int mm = mi * 64 + mt * 16 + g + p * 8;
                    const float v0 = cS[mt][j][p * 2] + b0;
                    const float v1 = cS[mt][j][p * 2 + 1] + b1;
                    __nv_bfloat16 h0, l0, h1, l1;
                    split2(v0, h0, l0);
                    split2(v1, h1, l1);
                    *(__nv_bfloat16*)(smem + nn * 256 + mm * 2) = h0;
                    *(__nv_bfloat16*)(smem + (nn + 1) * 256 + mm * 2) = h1;
                    *(__nv_bfloat16*)(smem + 32768 + nn * 256 + mm * 2) = l0;
                    *(__nv_bfloat16*)(smem + 32768 + (nn + 1) * 256 + mm * 2) = l1;
                }
            }
        }
        __syncthreads();
#pragma unroll
        for (int rr = 0; rr < 16; rr++) {
            const int r = warp + rr * 8;
            uint2 vh = *(uint2*)(smem + r * 256 + lane * 8);
            uint2 vl = *(uint2*)(smem + 32768 + r * 256 + lane * 8);
            *(uint2*)&g_vth[(size_t)(d0 + r) * NTOT + m0 + lane * 4] = vh;
            *(uint2*)&g_vtl[(size_t)(d0 + r) * NTOT + m0 + lane * 4] = vl;
        }
    }
}

// ---------------------------------------------------------------------------
// Kernel 2: 8-warp FA2 attention, split-K2, 2 CTAs/SM.
// Warps: 4 (mi rows) x 2 (ci). S: warp owns S[16 rows, 32 keys(ci)].
// PV: warp owns douts (vc*32 + ci*16) for 8 x 32-dout V chunks.
// P aliased into stream buffer B1; PA-hi in regs, PA-lo streamed.
// ---------------------------------------------------------------------------
#define QH_OFF 0
#define QL_OFF 33792
#define B0_OFF 67584
#define B1_OFF 86016
#define RD_OFF 104448
#define SM_ATT 105472

__global__ __launch_bounds__(256, 2) void attn_half() {
    extern __shared__ char smem[];
    const uint32_t sbase = smem_u32(smem);

    const int tid  = threadIdx.x;
    const int lane = tid & 31;
    const int warp = tid >> 5;
    const int mi   = warp & 3;
    const int ci   = warp >> 2;          // 0..1
    const int g    = lane >> 2;
    const int tg   = lane & 3;

    const uint32_t bRow  = (uint32_t)((lane >> 4) * 8 + (lane & 7));
    const uint32_t bC16  = (uint32_t)((lane >> 3) & 1) * 16;
    const uint32_t bOffK = ((uint32_t)ci * 32 + bRow) * 144 + bC16;       // + kq*2304 + st*32
    const uint32_t bOffV = ((uint32_t)ci * 16 + bRow) * 144 + bC16;       // + st*32
    const uint32_t aRow  = (uint32_t)(mi * 16 + (lane & 7) + (((lane >> 3) & 1) * 8));
    const uint32_t aOffQ = aRow * 528 + (uint32_t)((lane >> 4) & 1) * 16;
    const uint32_t aOffP = aRow * 144 + (uint32_t)((lane >> 4) & 1) * 16;

    int s = 0;
    while (s < 7 && (int)blockIdx.x >= c2_start[s + 1]) s++;
    const int li   = blockIdx.x - c2_start[s];
    const int gr   = c2_g[s];
    const int tile = li >> 1;
    const int half = li & 1;
    const int nk   = c_n_g[gr];
    const int koff = c_off_g[gr];
    const int q0   = koff + tile * 64;
    const int kv0  = koff + half * (nk >> 1);
    const int n_kt = nk >> 7;

    auto load_k = [&](uint32_t dst, int kb, int dc) {
#pragma unroll
        for (int p = 0; p < 4; p++) {
            int idx = p * 256 + tid;
            int comp = idx >> 9;
            int e = idx & 511;
            int r = e >> 3, c16 = e & 7;
            cp16(dst + comp * 9216 + r * 144 + c16 * 16,
                 (comp ? g_kl : g_kh) + (kb + r) * FEAT + dc * 64 + c16 * 8);
        }
    };
    // 32-dout V chunk into a 9216B half-buffer (hi @0, lo @4608)
    auto load_v = [&](uint32_t dst, int kb, int vc) {
#pragma unroll
        for (int p = 0; p < 2; p++) {
            int idx = p * 256 + tid;
            int comp = idx >> 8;
            int e = idx & 255;
            int r = e >> 3, c16 = e & 7;
            cp16(dst + comp * 4608 + r * 144 + c16 * 16,
                 (comp ? g_vtl : g_vth) + (size_t)(vc * 32 + r) * NTOT + kb + c16 * 8);
        }
    };

    // resident Q hi/lo [64][256], row stride 528B
#pragma unroll
    for (int p = 0; p < 16; p++) {
        int idx = p * 256 + tid;
        int comp = idx >> 11;
        int e = idx & 2047;
        int r = e >> 5, c16 = e & 31;
        cp16(sbase + (comp ? QL_OFF : QH_OFF) + r * 528 + c16 * 16,
             (comp ? g_ql : g_qh) + (q0 + r) * FEAT + c16 * 8);
    }
    cp_commit();
    cp_wait<0>();
    __syncthreads();

    float* red1 = (float*)(smem + RD_OFF);          // [2][64]
    float* red2 = (float*)(smem + RD_OFF + 512);    // [2][64]
    uint32_t* ph32 = (uint32_t*)(smem + B1_OFF);    // P hi alias
    uint32_t* pl32 = (uint32_t*)(smem + B1_OFF + 9216);

    float O[8][2][4];
#pragma unroll
    for (int a = 0; a < 8; a++)
#pragma unroll
        for (int b = 0; b < 2; b++)
#pragma unroll
            for (int c = 0; c < 4; c++) O[a][b][c] = 0.f;
    float M0 = -INFINITY, M1 = -INFINITY, L0 = 0.f, L1 = 0.f;
    const float scale = 0.0625f;
    const int row0 = mi * 16 + g;
    const int row1 = row0 + 8;

    for (int kt = 0; kt < n_kt; kt++) {
        const int kb = kv0 + kt * 64;

        // iter start: buffers free (prev iter fully consumed)
        __syncthreads();
        load_k(sbase + B0_OFF, kb, 0);
        cp_commit();

        float cS[4][4];
#pragma unroll
        for (int j = 0; j < 4; j++)
#pragma unroll
            for (int c = 0; c < 4; c++) cS[j][c] = 0.f;

        // ---------- S phase: K chunks 0..3 ----------
        for (int dc = 0; dc < 4; dc++) {
            cp_wait<0>();
            __syncthreads();
            if (dc < 3)
                load_k(sbase + (((dc + 1) & 1) ? B1_OFF : B0_OFF), kb, dc + 1);
            else
                load_v(sbase + B0_OFF, kb, 0);   // V chunk 0 into B0 half0
            cp_commit();

            const uint32_t khbuf = sbase + ((dc & 1) ? B1_OFF : B0_OFF);
            const uint32_t klbuf = khbuf + 9216;

#pragma unroll
            for (int st = 0; st < 4; st++) {
                const uint32_t stoff = (uint32_t)st * 32;
                uint32_t ah0, ah1, ah2, ah3, al0, al1, al2, al3;
                ldm_x4(ah0, ah1, ah2, ah3,
                       sbase + QH_OFF + aOffQ + (uint32_t)(dc * 4 + st) * 32);
                ldm_x4(al0, al1, al2, al3,
                       sbase + QL_OFF + aOffQ + (uint32_t)(dc * 4 + st) * 32);
#pragma unroll
                for (int kq = 0; kq < 2; kq++) {
                    uint32_t h0, h1, h2, h3, l0, l1, l2, l3;
                    ldm_x4(h0, h1, h2, h3,
                           khbuf + (uint32_t)kq * 2304 + bOffK + stoff);
                    ldm_x4(l0, l1, l2, l3,
                           klbuf + (uint32_t)kq * 2304 + bOffK + stoff);
                    hmma(cS[2 * kq], ah0, ah1, ah2, ah3, h0, h1);
                    hmma(cS[2 * kq + 1], ah0, ah1, ah2, ah3, h2, h3);
                    hmma(cS[2 * kq], ah0, ah1, ah2, ah3, l0, l1);
                    hmma(cS[2 * kq + 1], ah0, ah1, ah2, ah3, l2, l3);
                    hmma(cS[2 * kq], al0, al1, al2, al3, h0, h1);
                    hmma(cS[2 * kq + 1], al0, al1, al2, al3, h2, h3);
                }
            }
        }

        // ---------- softmax (cross-ci via smem; V0 load in flight) ----------
        float mx0 = -INFINITY, mx1 = -INFINITY;
#pragma unroll
        for (int j = 0; j < 4; j++) {
            mx0 = fmaxf(mx0, fmaxf(cS[j][0], cS[j][1]));
            mx1 = fmaxf(mx1, fmaxf(cS[j][2], cS[j][3]));
        }
        mx0 *= scale;
        mx1 *= scale;
        mx0 = fmaxf(mx0, __shfl_xor_sync(0xffffffffu, mx0, 1));
        mx0 = fmaxf(mx0, __shfl_xor_sync(0xffffffffu, mx0, 2));
        mx1 = fmaxf(mx1, __shfl_xor_sync(0xffffffffu, mx1, 1));
        mx1 = fmaxf(mx1, __shfl_xor_sync(0xffffffffu, mx1, 2));
        if (tg == 0) {
            red1[ci * 64 + row0] = mx0;
            red1[ci * 64 + row1] = mx1;
        }
        __syncthreads();   // red1 ready; also: all warps done reading B1 (K3)
        const float mall0 = fmaxf(red1[row0], red1[64 + row0]);
        const float mall1 = fmaxf(red1[row1], red1[64 + row1]);
        const float mn0 = fmaxf(M0, mall0);
        const float mn1 = fmaxf(M1, mall1);
        const float alpha0 = __expf(M0 - mn0);
        const float alpha1 = __expf(M1 - mn1);
        M0 = mn0;
        M1 = mn1;
        float ps0 = 0.f, ps1 = 0.f;
#pragma unroll
        for (int j = 0; j < 4; j++) {
            cS[j][0] = __expf(cS[j][0] * scale - mn0);
            cS[j][1] = __expf(cS[j][1] * scale - mn0);
            cS[j][2] = __expf(cS[j][2] * scale - mn1);
            cS[j][3] = __expf(cS[j][3] * scale - mn1);
            ps0 += cS[j][0] + cS[j][1];
            ps1 += cS[j][2] + cS[j][3];
        }
        ps0 += __shfl_xor_sync(0xffffffffu, ps0, 1);
        ps0 += __shfl_xor_sync(0xffffffffu, ps0, 2);
        ps1 += __shfl_xor_sync(0xffffffffu, ps1, 1);
        ps1 += __shfl_xor_sync(0xffffffffu, ps1, 2);

        // write P hi/lo into B1 alias (stride 144B) + partial sums
#pragma unroll
        for (int j = 0; j < 4; j++) {
            const int colw = ci * 16 + (j >> 1) * 8 + (j & 1) * 4 + tg;
            ph32[row0 * 36 + colw] = packsplit_hi(cS[j][0], cS[j][1]);
            ph32[row1 * 36 + colw] = packsplit_hi(cS[j][2], cS[j][3]);
            pl32[row0 * 36 + colw] = packsplit_lo(cS[j][0], cS[j][1]);
            pl32[row1 * 36 + colw] = packsplit_lo(cS[j][2], cS[j][3]);
        }
        if (tg == 0) {
            red2[ci * 64 + row0] = ps0;
            red2[ci * 64 + row1] = ps1;
        }
        __syncthreads();   // P + red2 visible
        L0 = L0 * alpha0 + red2[row0] + red2[64 + row0];
        L1 = L1 * alpha1 + red2[row1] + red2[64 + row1];

        const bool need_rescale =
            !__all_sync(0xffffffffu, (alpha0 == 1.0f) & (alpha1 == 1.0f));
        if (need_rescale) {
#pragma unroll
            for (int a = 0; a < 8; a++)
#pragma unroll
                for (int b = 0; b < 2; b++) {
                    O[a][b][0] *= alpha0;
                    O[a][b][1] *= alpha0;
                    O[a][b][2] *= alpha1;
                    O[a][b][3] *= alpha1;
                }
        }

        // PA hi frags in registers (16); lo streamed per step from the alias
        uint32_t PAh[4][4];
#pragma unroll
        for (int ks = 0; ks < 4; ks++)
            ldm_x4(PAh[ks][0], PAh[ks][1], PAh[ks][2], PAh[ks][3],
                   sbase + B1_OFF + aOffP + (uint32_t)ks * 32);

        // ---------- PV phase: 8 x 32-dout chunks, double-buffered in B0 ----------
        for (int vc = 0; vc < 8; vc++) {
            cp_wait<0>();
            __syncthreads();
            if (vc < 7) {
                load_v(sbase + B0_OFF + (((vc + 1) & 1) * 9216), kb, vc + 1);
                cp_commit();
            }
            const uint32_t vbuf = sbase + B0_OFF + ((vc & 1) * 9216);

#pragma unroll
            for (int st = 0; st < 4; st++) {
                const uint32_t stoff = (uint32_t)st * 32;
                uint32_t h0, h1, h2, h3, l0, l1, l2, l3, p0, p1, p2, p3;
                ldm_x4(h0, h1, h2, h3, vbuf + bOffV + stoff);
                ldm_x4(l0, l1, l2, l3, vbuf + 4608 + bOffV + stoff);
                ldm_x4(p0, p1, p2, p3,
                       sbase + B1_OFF + 9216 + aOffP + (uint32_t)st * 32);
                hmma(O[vc][0], PAh[st][0], PAh[st][1], PAh[st][2], PAh[st][3],
                     h0, h1);
                hmma(O[vc][1], PAh[st][0], PAh[st][1], PAh[st][2], PAh[st][3],
                     h2, h3);
                hmma(O[vc][0], PAh[st][0], PAh[st][1], PAh[st][2], PAh[st][3],
                     l0, l1);
                hmma(O[vc][1], PAh[st][0], PAh[st][1], PAh[st][2], PAh[st][3],
                     l2, l3);
                hmma(O[vc][0], p0, p1, p2, p3, h0, h1);
                hmma(O[vc][1], p0, p1, p2, p3, h2, h3);
            }
        }
    }

    // ---------- epilogue: unnormalized partials + (M, L) ----------
    const int gr0 = q0 + row0;
    const int gr1 = q0 + row1;
    float* acc = g_acc + (size_t)half * NTOT * FEAT;
#pragma unroll
    for (int vc = 0; vc < 8; vc++)
#pragma unroll
        for (int j8 = 0; j8 < 2; j8++) {
            const int col = vc * 32 + ci * 16 + j8 * 8 + tg * 2;
            float2 o0, o1;
            o0.x = O[vc][j8][0];
            o0.y = O[vc][j8][1];
            o1.x = O[vc][j8][2];
            o1.y = O[vc][j8][3];
            *(float2*)&acc[(size_t)gr0 * FEAT + col] = o0;
            *(float2*)&acc[(size_t)gr1 * FEAT + col] = o1;
        }
    if (ci == 0 && tg == 0) {
        float* ml = g_ml + (size_t)half * NTOT * 2;
        ml[gr0 * 2 + 0] = M0;
        ml[gr0 * 2 + 1] = L0;
        ml[gr1 * 2 + 0] = M1;
        ml[gr1 * 2 + 1] = L1;
    }
}

// ---------------------------------------------------------------------------
// Kernel 3: combine the two key-half partials
// ---------------------------------------------------------------------------
__global__ __launch_bounds__(256) void combine(float* __restrict__ out) {
    const int idx = blockIdx.x * 256 + threadIdx.x;
    const int row = idx >> 6;
    const int col = (idx & 63) * 4;

    const float m0 = g_ml[row * 2 + 0];
    const float l0 = g_ml[row * 2 + 1];
    const float m1 = g_ml[NTOT * 2 + row * 2 + 0];
    const float l1 = g_ml[NTOT * 2 + row * 2 + 1];
    const float M = fmaxf(m0, m1);
    const float a0 = __expf(m0 - M);
    const float a1 = __expf(m1 - M);
    const float inv = 1.0f / (a0 * l0 + a1 * l1);

    const float4 o0 = *(const float4*)&g_acc[(size_t)row * FEAT + col];
    const float4 o1 = *(const float4*)&g_acc[(size_t)(NTOT + row) * FEAT + col];
    float4 o;
    o.x = (a0 * o0.x + a1 * o1.x) * inv;
    o.y = (a0 * o0.y + a1 * o1.y) * inv;
    o.z = (a0 * o0.z + a1 * o1.z) * inv;
    o.w = (a0 * o0.w + a1 * o1.w) * inv;
    *(float4*)&out[(size_t)row * FEAT + col] = o;
}

// ---------------------------------------------------------------------------
extern "C" void kernel_launch(void* const* d_in, const int* in_sizes, int n_in,
                              void* d_out, int out_size) {
    const float* s    = (const float*)d_in[0];   // [12288, 256]
    const float* W    = (const float*)d_in[1];   // [256, 768]
    const float* bias = (const float*)d_in[2];   // [768]
    float* out = (float*)d_out;                  // [12288, 256]

    cudaFuncSetAttribute(qkv_hmma, cudaFuncAttributeMaxDynamicSharedMemorySize,
                         GM_TOTAL);
    cudaFuncSetAttribute(attn_half, cudaFuncAttributeMaxDynamicSharedMemorySize,
                         SM_ATT);

    split_s<<<3072, 256>>>(s);
    split_w<<<768, 256>>>(W);
    qkv_hmma<<<dim3(6, 96), 256, GM_TOTAL>>>(bias);
    attn_half<<<384, 256, SM_ATT>>>();
    combine<<<3072, 256>>>(out);
}

// round 14
// speedup vs baseline: 1.1462x; 1.0660x over previous
#include <cuda_runtime.h>
#include <cuda_bf16.h>
#include <math.h>
#include <stdint.h>

#define FEAT 256
#define NQKV 768
#define NTOT 12288

// bf16 hi/lo splits (device globals: allocation-guard safe)
__device__ __nv_bfloat16 g_qh[NTOT * FEAT];
__device__ __nv_bfloat16 g_ql[NTOT * FEAT];
__device__ __nv_bfloat16 g_kh[NTOT * FEAT];
__device__ __nv_bfloat16 g_kl[NTOT * FEAT];
__device__ __nv_bfloat16 g_vth[FEAT * NTOT];   // V transposed: [d][key]
__device__ __nv_bfloat16 g_vtl[FEAT * NTOT];
// split inputs for the QKV HMMA GEMM
__device__ __nv_bfloat16 g_sh[NTOT * FEAT];
__device__ __nv_bfloat16 g_sl[NTOT * FEAT];
__device__ __nv_bfloat16 g_wth[NQKV * FEAT];   // W transposed: [n][k]
__device__ __nv_bfloat16 g_wtl[NQKV * FEAT];
// split-K attention scratch
__device__ float g_acc[2 * NTOT * FEAT];
__device__ float g_ml[2 * NTOT * 2];

__constant__ int c_n_g[8]   = {2048, 1536, 1024, 2048, 512, 1792, 1280, 2048};
__constant__ int c_off_g[8] = {0, 2048, 3584, 4608, 6656, 7168, 8960, 10240};
// 384 half-CTAs, LPT order
__constant__ int c2_start[9] = {0, 64, 128, 192, 248, 296, 336, 368, 384};
__constant__ int c2_g[8]     = {0, 3, 7, 5, 1, 6, 2, 4};

// ---------------------------------------------------------------------------
// helpers
// ---------------------------------------------------------------------------
__device__ __forceinline__ uint32_t smem_u32(const void* p) {
    uint32_t a;
    asm("{ .reg .u64 t; cvta.to.shared.u64 t, %1; cvt.u32.u64 %0, t; }"
        : "=r"(a) : "l"(p));
    return a;
}
__device__ __forceinline__ void cp16(uint32_t dst, const void* src) {
    asm volatile(
        "{ .reg .u64 g; cvta.to.global.u64 g, %1;\n\t"
        "cp.async.cg.shared.global [%0], [g], 16; }"
        ::"r"(dst), "l"(src));
}
__device__ __forceinline__ void cp_commit() {
    asm volatile("cp.async.commit_group;" ::: "memory");
}
template <int N>
__device__ __forceinline__ void cp_wait() {
    asm volatile("cp.async.wait_group %0;" ::"n"(N) : "memory");
}
__device__ __forceinline__ void hmma(float* c, uint32_t a0, uint32_t a1,
                                     uint32_t a2, uint32_t a3,
                                     uint32_t b0, uint32_t b1) {
    asm volatile(
        "mma.sync.aligned.m16n8k16.row.col.f32.bf16.bf16.f32 "
        "{%0,%1,%2,%3}, {%4,%5,%6,%7}, {%8,%9}, {%0,%1,%2,%3};"
        : "+f"(c[0]), "+f"(c[1]), "+f"(c[2]), "+f"(c[3])
        : "r"(a0), "r"(a1), "r"(a2), "r"(a3), "r"(b0), "r"(b1));
}
__device__ __forceinline__ void ldm_x4(uint32_t& r0, uint32_t& r1, uint32_t& r2,
                                       uint32_t& r3, uint32_t addr) {
    asm volatile(
        "ldmatrix.sync.aligned.m8n8.x4.shared.b16 {%0,%1,%2,%3}, [%4];"
        : "=r"(r0), "=r"(r1), "=r"(r2), "=r"(r3) : "r"(addr));
}
__device__ __forceinline__ void split2(float x, __nv_bfloat16& h, __nv_bfloat16& l) {
    h = __float2bfloat16(x);
    l = __float2bfloat16(x - __bfloat162float(h));
}
__device__ __forceinline__ uint32_t packsplit_hi(float a, float b) {
    __nv_bfloat16 ha = __float2bfloat16(a), hb = __float2bfloat16(b);
    return (uint32_t)__bfloat16_as_ushort(ha) |
           ((uint32_t)__bfloat16_as_ushort(hb) << 16);
}
__device__ __forceinline__ uint32_t packsplit_lo(float a, float b) {
    __nv_bfloat16 ha = __float2bfloat16(a), hb = __float2bfloat16(b);
    __nv_bfloat16 la = __float2bfloat16(a - __bfloat162float(ha));
    __nv_bfloat16 lb = __float2bfloat16(b - __bfloat162float(hb));
    return (uint32_t)__bfloat16_as_ushort(la) |
           ((uint32_t)__bfloat16_as_ushort(lb) << 16);
}

// ---------------------------------------------------------------------------
// Kernel 0: fused input splits (s and W^T)
// blocks 0..3071: split s (4 floats/thread). blocks 3072..3839: split+transpose W.
// ---------------------------------------------------------------------------
__global__ __launch_bounds__(256) void split_sw(const float* __restrict__ S,
                                                const float* __restrict__ W) {
    if (blockIdx.x < 3072) {
        int i4 = blockIdx.x * 256 + threadIdx.x;
        const float4 v = *(const float4*)&S[i4 * 4];
        __nv_bfloat16 h[4], l[4];
        split2(v.x, h[0], l[0]);
        split2(v.y, h[1], l[1]);
        split2(v.z, h[2], l[2]);
        split2(v.w, h[3], l[3]);
        uint2 ph, pl;
        ph.x = (uint32_t)__bfloat16_as_ushort(h[0]) |
               ((uint32_t)__bfloat16_as_ushort(h[1]) << 16);
        ph.y = (uint32_t)__bfloat16_as_ushort(h[2]) |
               ((uint32_t)__bfloat16_as_ushort(h[3]) << 16);
        pl.x = (uint32_t)__bfloat16_as_ushort(l[0]) |
               ((uint32_t)__bfloat16_as_ushort(l[1]) << 16);
        pl.y = (uint32_t)__bfloat16_as_ushort(l[2]) |
               ((uint32_t)__bfloat16_as_ushort(l[3]) << 16);
        *(uint2*)&g_sh[i4 * 4] = ph;
        *(uint2*)&g_sl[i4 * 4] = pl;
    } else {
        int t = (blockIdx.x - 3072) * 256 + threadIdx.x;
        int k = t / NQKV, n = t % NQKV;
        __nv_bfloat16 h, l;
        split2(W[t], h, l);
        g_wth[n * FEAT + k] = h;
        g_wtl[n * FEAT + k] = l;
    }
}

// ---------------------------------------------------------------------------
// Kernel 1: QKV GEMM — BM=128, BN=64, 2 CTAs/SM, ldmatrix single-sync pipeline.
// 8 warps: mi = warp>>1 (m32), nis = warp&1 (n32). 4 k-chunks of 64.
// smem: stage s (0/1) at s*55296: A (36864B: hi@0, lo@18432), B @+36864
//       (18432B: hi@0, lo@9216). Total 110592.
// ---------------------------------------------------------------------------
#define GM_TOTAL 110592

__global__ __launch_bounds__(256, 2) void qkv_hmma(const float* __restrict__ bias) {
    extern __shared__ char smem[];
    const uint32_t sbase = smem_u32(smem);

    const int tid  = threadIdx.x;
    const int lane = tid & 31;
    const int warp = tid >> 5;
    const int mi   = warp >> 1;          // 0..3 (32-row block)
    const int nis  = warp & 1;           // 0..1 (32-col block)
    const int g    = lane >> 2;
    const int tg   = lane & 3;

    const int nblk = blockIdx.x;         // 0..11
    const int n0   = nblk * 64;
    const int m0   = blockIdx.y * 128;

    const uint32_t aOff = (uint32_t)(mi * 32 + (lane & 7) + (((lane >> 3) & 1) * 8)) * 144 +
                          (uint32_t)((lane >> 4) & 1) * 16;
    const uint32_t bOff = (uint32_t)(nis * 32 + ((lane >> 4) * 8) + (lane & 7)) * 144 +
                          (uint32_t)((lane >> 3) & 1) * 16;

    float cS[2][4][4];
#pragma unroll
    for (int a = 0; a < 2; a++)
#pragma unroll
        for (int b = 0; b < 4; b++)
#pragma unroll
            for (int c = 0; c < 4; c++) cS[a][b][c] = 0.f;

    auto load_stage = [&](int kc, uint32_t buf) {
        // A: 128 rows x 8 c16 x 2 comps = 2048 cp16 (8/thread)
#pragma unroll
        for (int p = 0; p < 8; p++) {
            int idx = p * 256 + tid;
            int comp = idx >> 10;
            int e = idx & 1023;
            int r = e >> 3, c16 = e & 7;
            cp16(sbase + buf + comp * 18432 + r * 144 + c16 * 16,
                 (comp ? g_sl : g_sh) + (m0 + r) * FEAT + kc * 64 + c16 * 8);
        }
        // B: 64 rows x 8 c16 x 2 comps = 1024 cp16 (4/thread)
#pragma unroll
        for (int p = 0; p < 4; p++) {
            int idx = p * 256 + tid;
            int comp = idx >> 9;
            int e = idx & 511;
            int r = e >> 3, c16 = e & 7;
            cp16(sbase + buf + 36864 + comp * 9216 + r * 144 + c16 * 16,
                 (comp ? g_wtl : g_wth) + (n0 + r) * FEAT + kc * 64 + c16 * 8);
        }
    };

    load_stage(0, 0);
    cp_commit();

    for (int kc = 0; kc < 4; kc++) {
        cp_wait<0>();
        __syncthreads();
        if (kc < 3) {
            load_stage(kc + 1, ((kc + 1) & 1) ? 55296u : 0u);
            cp_commit();
        }
        const uint32_t abuf = sbase + ((kc & 1) ? 55296u : 0u);
        const uint32_t albuf = abuf + 18432u;
        const uint32_t bbuf = abuf + 36864u;
        const uint32_t blbuf = bbuf + 9216u;

#pragma unroll
        for (int st = 0; st < 4; st++) {
            const uint32_t so = (uint32_t)st * 32;
            uint32_t Ah[2][4], Al[2][4];
#pragma unroll
            for (int mt = 0; mt < 2; mt++) {
                ldm_x4(Ah[mt][0], Ah[mt][1], Ah[mt][2], Ah[mt][3],
                       abuf + (uint32_t)mt * 2304 + aOff + so);
                ldm_x4(Al[mt][0], Al[mt][1], Al[mt][2], Al[mt][3],
                       albuf + (uint32_t)mt * 2304 + aOff + so);
            }
#pragma unroll
            for (int jp = 0; jp < 2; jp++) {
                uint32_t h0, h1, h2, h3, l0, l1, l2, l3;
                ldm_x4(h0, h1, h2, h3, bbuf + (uint32_t)jp * 2304 + bOff + so);
                ldm_x4(l0, l1, l2, l3, blbuf + (uint32_t)jp * 2304 + bOff + so);
#pragma unroll
                for (int mt = 0; mt < 2; mt++) {
                    hmma(cS[mt][jp * 2], Ah[mt][0], Ah[mt][1], Ah[mt][2],
                         Ah[mt][3], h0, h1);
                    hmma(cS[mt][jp * 2], Ah[mt][0], Ah[mt][1], Ah[mt][2],
                         Ah[mt][3], l0, l1);
                    hmma(cS[mt][jp * 2], Al[mt][0], Al[mt][1], Al[mt][2],
                         Al[mt][3], h0, h1);
                    hmma(cS[mt][jp * 2 + 1], Ah[mt][0], Ah[mt][1], Ah[mt][2],
                         Ah[mt][3], h2, h3);
                    hmma(cS[mt][jp * 2 + 1], Ah[mt][0], Ah[mt][1], Ah[mt][2],
                         Ah[mt][3], l2, l3);
                    hmma(cS[mt][jp * 2 + 1], Al[mt][0], Al[mt][1], Al[mt][2],
                         Al[mt][3], h2, h3);
                }
            }
        }
    }

    __syncthreads();

    if (nblk < 8) {
        // Q (nblk 0..3) or K (nblk 4..7): direct packed stores
        __nv_bfloat16* Bh = (nblk < 4) ? g_qh : g_kh;
        __nv_bfloat16* Bl = (nblk < 4) ? g_ql : g_kl;
        const int cbase0 = (n0 & 255) + nis * 32;
        const int bbase  = (nblk < 4) ? 0 : 256;
#pragma unroll
        for (int mt = 0; mt < 2; mt++) {
#pragma unroll
            for (int j = 0; j < 4; j++) {
                const int cc = cbase0 + j * 8 + tg * 2;
                const float b0 = bias[bbase + cc];
                const float b1 = bias[bbase + cc + 1];
#pragma unroll
                for (int p = 0; p < 2; p++) {
                    const int row = m0 + mi * 32 + mt * 16 + g + p * 8;
                    const float v0 = cS[mt][j][p * 2] + b0;
                    const float v1 = cS[mt][j][p * 2 + 1] + b1;
                    *(uint32_t*)&Bh[row * FEAT + cc] = packsplit_hi(v0, v1);
                    *(uint32_t*)&Bl[row * FEAT + cc] = packsplit_lo(v0, v1);
                }
            }
        }
    } else {
        // V: stage [nn][mm] bf16 hi/lo (hi @0 16KB, lo @16384), coalesced store
        const int d0 = n0 - 512;
#pragma unroll
        for (int mt = 0; mt < 2; mt++) {
#pragma unroll
            for (int j = 0; j < 4; j++) {
                const int nn = nis * 32 + j * 8 + tg * 2;
                const float b0 = bias[512 + d0 + nn];
                const float b1 = bias[512 + d0 + nn + 1];
#pragma unroll
                for (int p = 0; p < 2; p++) {
                    const int mm = mi * 32 + mt * 16 + g + p * 8;
                    const float v0 = cS[mt][j][p * 2] + b0;
                    const float v1 = cS[mt][j][p * 2 + 1] + b1;
                    __nv_bfloat16 h0, l0, h1, l1;
                    split2(v0, h0, l0);
                    split2(v1, h1, l1);
                    *(__nv_bfloat16*)(smem + nn * 256 + mm * 2) = h0;
                    *(__nv_bfloat16*)(smem + (nn + 1) * 256 + mm * 2) = h1;
                    *(__nv_bfloat16*)(smem + 16384 + nn * 256 + mm * 2) = l0;
                    *(__nv_bfloat16*)(smem + 16384 + (nn + 1) * 256 + mm * 2) = l1;
                }
            }
        }
        __syncthreads();
#pragma unroll
        for (int rr = 0; rr < 8; rr++) {
            const int r = warp + rr * 8;     // 64 n-rows
            uint2 vh = *(uint2*)(smem + r * 256 + lane * 8);
            uint2 vl = *(uint2*)(smem + 16384 + r * 256 + lane * 8);
            *(uint2*)&g_vth[(size_t)(d0 + r) * NTOT + m0 + lane * 4] = vh;
            *(uint2*)&g_vtl[(size_t)(d0 + r) * NTOT + m0 + lane * 4] = vl;
        }
    }
}

// ---------------------------------------------------------------------------
// Kernel 2: FA2 HMMA attention, split-K, ldmatrix, single-sync flat pipeline.
// (Exact R10 version — best measured: 188 us.)
// BM=64 (4 warps x m16), BN=64 keys/iter. 384 CTAs -> 2/SM.
// ---------------------------------------------------------------------------
#define QH_OFF 0
#define QL_OFF 33792
#define B0_OFF 67584
#define B1_OFF 86016
#define SM_TOTAL 104448

__global__ __launch_bounds__(128, 2) void attn_half() {
    extern __shared__ char smem[];
    const uint32_t sbase = smem_u32(smem);

    const int tid  = threadIdx.x;
    const int lane = tid & 31;
    const int mi   = tid >> 5;
    const int g    = lane >> 2;
    const int tg   = lane & 3;

    const uint32_t bOff = ((uint32_t)(lane >> 4) * 8 + (lane & 7)) * 144 +
                          (((uint32_t)(lane >> 3) & 1) * 16);
    const uint32_t aOffQ = ((uint32_t)(mi * 16 + (lane & 7) + (((lane >> 3) & 1) * 8))) * 528 +
                           (((uint32_t)(lane >> 4) & 1) * 16);

    int s = 0;
    while (s < 7 && (int)blockIdx.x >= c2_start[s + 1]) s++;
    const int li   = blockIdx.x - c2_start[s];
    const int gr   = c2_g[s];
    const int tile = li >> 1;
    const int half = li & 1;
    const int nk   = c_n_g[gr];
    const int koff = c_off_g[gr];
    const int q0   = koff + tile * 64;
    const int kv0  = koff + half * (nk >> 1);
    const int n_kt = nk >> 7;

    auto load_k = [&](uint32_t dst, int kb, int dc) {
#pragma unroll
        for (int p = 0; p < 8; p++) {
            int idx = p * 128 + tid;
            int comp = idx >> 9;
            int e = idx & 511;
            int r = e >> 3, c16 = e & 7;
            cp16(dst + comp * 9216 + r * 144 + c16 * 16,
                 (comp ? g_kl : g_kh) + (kb + r) * FEAT + dc * 64 + c16 * 8);
        }
    };
    auto load_v = [&](uint32_t dst, int kb, int vc) {
#pragma unroll
        for (int p = 0; p < 8; p++) {
            int idx = p * 128 + tid;
            int comp = idx >> 9;
            int e = idx & 511;
            int r = e >> 3, c16 = e & 7;
            cp16(dst + comp * 9216 + r * 144 + c16 * 16,
                 (comp ? g_vtl : g_vth) + (size_t)(vc * 64 + r) * NTOT + kb + c16 * 8);
        }
    };

    // resident Q hi/lo [64][256]
#pragma unroll
    for (int p = 0; p < 32; p++) {
        int idx = p * 128 + tid;
        int comp = idx >> 11;
        int e = idx & 2047;
        int r = e >> 5, c16 = e & 31;
        cp16(sbase + (comp ? QL_OFF : QH_OFF) + r * 528 + c16 * 16,
             (comp ? g_ql : g_qh) + (q0 + r) * FEAT + c16 * 8);
    }
    cp_commit();
    cp_wait<0>();
    __syncthreads();

    float O[4][8][4];
#pragma unroll
    for (int a = 0; a < 4; a++)
#pragma unroll
        for (int b = 0; b < 8; b++)
#pragma unroll
            for (int c = 0; c < 4; c++) O[a][b][c] = 0.f;
    float M0 = -INFINITY, M1 = -INFINITY, L0 = 0.f, L1 = 0.f;
    const float scale = 0.0625f;

    load_k(sbase + B0_OFF, kv0, 0);
    cp_commit();

    for (int kt = 0; kt < n_kt; kt++) {
        const int kb = kv0 + kt * 64;

        float cS[8][4];
#pragma unroll
        for (int j = 0; j < 8; j++)
#pragma unroll
            for (int c = 0; c < 4; c++) cS[j][c] = 0.f;

        // ---------- S phase: stages K0..K3 ----------
        for (int dc = 0; dc < 4; dc++) {
            cp_wait<0>();
            __syncthreads();
            if (dc < 3)
                load_k(sbase + (((dc + 1) & 1) ? B1_OFF : B0_OFF), kb, dc + 1);
            else
                load_v(sbase + B0_OFF, kb, 0);
            cp_commit();

            const uint32_t khbuf = sbase + ((dc & 1) ? B1_OFF : B0_OFF);
            const uint32_t klbuf = khbuf + 9216;

#pragma unroll
            for (int st = 0; st < 4; st++) {
                const uint32_t stoff = (uint32_t)st * 32;
                uint32_t ah0, ah1, ah2, ah3, al0, al1, al2, al3;
                ldm_x4(ah0, ah1, ah2, ah3,
                       sbase + QH_OFF + aOffQ + (uint32_t)(dc * 4 + st) * 32);
                ldm_x4(al0, al1, al2, al3,
                       sbase + QL_OFF + aOffQ + (uint32_t)(dc * 4 + st) * 32);
#pragma unroll
                for (int a = 0; a < 4; a++) {
                    uint32_t h0, h1, h2, h3, l0, l1, l2, l3;
                    ldm_x4(h0, h1, h2, h3, khbuf + (uint32_t)a * 2304 + bOff + stoff);
                    ldm_x4(l0, l1, l2, l3, klbuf + (uint32_t)a * 2304 + bOff + stoff);
                    hmma(cS[2 * a], ah0, ah1, ah2, ah3, h0, h1);
                    hmma(cS[2 * a], ah0, ah1, ah2, ah3, l0, l1);
                    hmma(cS[2 * a], al0, al1, al2, al3, h0, h1);
                    hmma(cS[2 * a + 1], ah0, ah1, ah2, ah3, h2, h3);
                    hmma(cS[2 * a + 1], ah0, ah1, ah2, ah3, l2, l3);
                    hmma(cS[2 * a + 1], al0, al1, al2, al3, h2, h3);
                }
            }
        }

        // ---------- warp-local online softmax (V0 load in flight) ----------
        float mx0 = -INFINITY, mx1 = -INFINITY;
#pragma unroll
        for (int j = 0; j < 8; j++) {
            mx0 = fmaxf(mx0, fmaxf(cS[j][0], cS[j][1]));
            mx1 = fmaxf(mx1, fmaxf(cS[j][2], cS[j][3]));
        }
        mx0 *= scale;
        mx1 *= scale;
        mx0 = fmaxf(mx0, __shfl_xor_sync(0xffffffffu, mx0, 1));
        mx0 = fmaxf(mx0, __shfl_xor_sync(0xffffffffu, mx0, 2));
        mx1 = fmaxf(mx1, __shfl_xor_sync(0xffffffffu, mx1, 1));
        mx1 = fmaxf(mx1, __shfl_xor_sync(0xffffffffu, mx1, 2));
        const float mn0 = fmaxf(M0, mx0);
        const float mn1 = fmaxf(M1, mx1);
        const float alpha0 = __expf(M0 - mn0);
        const float alpha1 = __expf(M1 - mn1);
        M0 = mn0;
        M1 = mn1;
        float ps0 = 0.f, ps1 = 0.f;
#pragma unroll
        for (int j = 0; j < 8; j++) {
            cS[j][0] = __expf(cS[j][0] * scale - mn0);
            cS[j][1] = __expf(cS[j][1] * scale - mn0);
            cS[j][2] = __expf(cS[j][2] * scale - mn1);
            cS[j][3] = __expf(cS[j][3] * scale - mn1);
            ps0 += cS[j][0] + cS[j][1];
            ps1 += cS[j][2] + cS[j][3];
        }
        ps0 += __shfl_xor_sync(0xffffffffu, ps0, 1);
        ps0 += __shfl_xor_sync(0xffffffffu, ps0, 2);
        ps1 += __shfl_xor_sync(0xffffffffu, ps1, 1);
        ps1 += __shfl_xor_sync(0xffffffffu, ps1, 2);
        L0 = L0 * alpha0 + ps0;
        L1 = L1 * alpha1 + ps1;

        const bool need_rescale =
            !__all_sync(0xffffffffu, (alpha0 == 1.0f) & (alpha1 == 1.0f));
        if (need_rescale) {
#pragma unroll
            for (int a = 0; a < 4; a++)
#pragma unroll
                for (int b = 0; b < 8; b++) {
                    O[a][b][0] *= alpha0;
                    O[a][b][1] *= alpha0;
                    O[a][b][2] *= alpha1;
                    O[a][b][3] *= alpha1;
                }
        }

        uint32_t PAh[4][4], PAl[4][4];
#pragma unroll
        for (int ks = 0; ks < 4; ks++) {
            PAh[ks][0] = packsplit_hi(cS[2 * ks][0], cS[2 * ks][1]);
            PAh[ks][1] = packsplit_hi(cS[2 * ks][2], cS[2 * ks][3]);
            PAh[ks][2] = packsplit_hi(cS[2 * ks + 1][0], cS[2 * ks + 1][1]);
            PAh[ks][3] = packsplit_hi(cS[2 * ks + 1][2], cS[2 * ks + 1][3]);
            PAl[ks][0] = packsplit_lo(cS[2 * ks][0], cS[2 * ks][1]);
            PAl[ks][1] = packsplit_lo(cS[2 * ks][2], cS[2 * ks][3]);
            PAl[ks][2] = packsplit_lo(cS[2 * ks + 1][0], cS[2 * ks + 1][1]);
            PAl[ks][3] = packsplit_lo(cS[2 * ks + 1][2], cS[2 * ks + 1][3]);
        }

        // ---------- PV phase: stages V0..V3 ----------
        for (int vc = 0; vc < 4; vc++) {
            cp_wait<0>();
            __syncthreads();
            if (vc < 3) {
                load_v(sbase + (((vc + 1) & 1) ? B1_OFF : B0_OFF), kb, vc + 1);
                cp_commit();
            } else if (kt + 1 < n_kt) {
                load_k(sbase + B0_OFF, kb + 64, 0);
                cp_commit();
            }

            const uint32_t vhbuf = sbase + ((vc & 1) ? B1_OFF : B0_OFF);
            const uint32_t vlbuf = vhbuf + 9216;

#pragma unroll
            for (int st = 0; st < 4; st++) {
                const uint32_t stoff = (uint32_t)st * 32;
#pragma unroll
                for (int a = 0; a < 4; a++) {
                    uint32_t h0, h1, h2, h3, l0, l1, l2, l3;
                    ldm_x4(h0, h1, h2, h3, vhbuf + (uint32_t)a * 2304 + bOff + stoff);
                    ldm_x4(l0, l1, l2, l3, vlbuf + (uint32_t)a * 2304 + bOff + stoff);
                    hmma(O[vc][2 * a], PAh[st][0], PAh[st][1], PAh[st][2],
                         PAh[st][3], h0, h1);
                    hmma(O[vc][2 * a], PAh[st][0], PAh[st][1], PAh[st][2],
                         PAh[st][3], l0, l1);
                    hmma(O[vc][2 * a], PAl[st][0], PAl[st][1], PAl[st][2],
                         PAl[st][3], h0, h1);
                    hmma(O[vc][2 * a + 1], PAh[st][0], PAh[st][1], PAh[st][2],
                         PAh[st][3], h2, h3);
                    hmma(O[vc][2 * a + 1], PAh[st][0], PAh[st][1], PAh[st][2],
                         PAh[st][3], l2, l3);
                    hmma(O[vc][2 * a + 1], PAl[st][0], PAl[st][1], PAl[st][2],
                         PAl[st][3], h2, h3);
                }
            }
        }
    }

    // ---------- epilogue ----------
    const int row0 = q0 + mi * 16 + g;
    const int row1 = row0 + 8;
    float* acc = g_acc + (size_t)half * NTOT * FEAT;
#pragma unroll
    for (int vc = 0; vc < 4; vc++)
#pragma unroll
        for (int j = 0; j < 8; j++) {
            const int col = vc * 64 + j * 8 + tg * 2;
            float2 o0, o1;
            o0.x = O[vc][j][0];
            o0.y = O[vc][j][1];
            o1.x = O[vc][j][2];
            o1.y = O[vc][j][3];
            *(float2*)&acc[(size_t)row0 * FEAT + col] = o0;
            *(float2*)&acc[(size_t)row1 * FEAT + col] = o1;
        }
    if (tg == 0) {
        float* ml = g_ml + (size_t)half * NTOT * 2;
        ml[row0 * 2 + 0] = M0;
        ml[row0 * 2 + 1] = L0;
        ml[row1 * 2 + 0] = M1;
        ml[row1 * 2 + 1] = L1;
    }
}

// ---------------------------------------------------------------------------
// Kernel 3: combine the two key-half partials
// ---------------------------------------------------------------------------
__global__ __launch_bounds__(256) void combine(float* __restrict__ out) {
    const int idx = blockIdx.x * 256 + threadIdx.x;
    const int row = idx >> 6;
    const int col = (idx & 63) * 4;

    const float m0 = g_ml[row * 2 + 0];
    const float l0 = g_ml[row * 2 + 1];
    const float m1 = g_ml[NTOT * 2 + row * 2 + 0];
    const float l1 = g_ml[NTOT * 2 + row * 2 + 1];
    const float M = fmaxf(m0, m1);
    const float a0 = __expf(m0 - M);
    const float a1 = __expf(m1 - M);
    const float inv = 1.0f / (a0 * l0 + a1 * l1);

    const float4 o0 = *(const float4*)&g_acc[(size_t)row * FEAT + col];
    const float4 o1 = *(const float4*)&g_acc[(size_t)(NTOT + row) * FEAT + col];
    float4 o;
    o.x = (a0 * o0.x + a1 * o1.x) * inv;
    o.y = (a0 * o0.y + a1 * o1.y) * inv;
    o.z = (a0 * o0.z + a1 * o1.z) * inv;
    o.w = (a0 * o0.w + a1 * o1.w) * inv;
    *(float4*)&out[(size_t)row * FEAT + col] = o;
}

// ---------------------------------------------------------------------------
extern "C" void kernel_launch(void* const* d_in, const int* in_sizes, int n_in,
                              void* d_out, int out_size) {
    const float* s    = (const float*)d_in[0];   // [12288, 256]
    const float* W    = (const float*)d_in[1];   // [256, 768]
    const float* bias = (const float*)d_in[2];   // [768]
    float* out = (float*)d_out;                  // [12288, 256]

    cudaFuncSetAttribute(qkv_hmma, cudaFuncAttributeMaxDynamicSharedMemorySize,
                         GM_TOTAL);
    cudaFuncSetAttribute(attn_half, cudaFuncAttributeMaxDynamicSharedMemorySize,
                         SM_TOTAL);

    split_sw<<<3840, 256>>>(s, W);
    qkv_hmma<<<dim3(12, 96), 256, GM_TOTAL>>>(bias);
    attn_half<<<384, 128, SM_TOTAL>>>();
    combine<<<3072, 256>>>(out);
}